// round 16
// baseline (speedup 1.0000x reference)
#include <cuda_runtime.h>
#include <cuda_fp16.h>
#include <math.h>
#include <stdint.h>

#define Bb 4
#define Ss 2048
#define Dd 1024
#define Hh 512
#define Ee 8
#define Ff 2816
#define Rr 16
#define HIDk 128
#define Nn 8192
#define NP 16384
#define LN_EPS 1e-5f

// ===================== baseline-PTX helpers =====================
__device__ __forceinline__ uint32_t smem_u32(const void* p) {
    uint32_t a;
    asm("{ .reg .u64 t; cvta.to.shared.u64 t, %1; cvt.u32.u64 %0, t; }" : "=r"(a) : "l"(p));
    return a;
}

#define CPASYNC16(dst, src) \
    asm volatile("cp.async.cg.shared.global [%0], [%1], 16;\n" :: "r"(dst), "l"(src))
#define CPASYNC16_CA(dst, src) \
    asm volatile("cp.async.ca.shared.global [%0], [%1], 16;\n" :: "r"(dst), "l"(src))
#define CP_COMMIT() asm volatile("cp.async.commit_group;\n" ::: "memory")
#define CP_WAIT(N)  asm volatile("cp.async.wait_group %0;\n" :: "n"(N) : "memory")

#define LDSM4(R, addr) \
    asm volatile("ldmatrix.sync.aligned.m8n8.x4.shared.b16 {%0,%1,%2,%3}, [%4];" \
        : "=r"((R)[0]), "=r"((R)[1]), "=r"((R)[2]), "=r"((R)[3]) : "r"(addr))

#define MMA16816(C, A, B0, B1) \
    asm volatile("mma.sync.aligned.m16n8k16.row.col.f32.f16.f16.f32 " \
        "{%0,%1,%2,%3}, {%4,%5,%6,%7}, {%8,%9}, {%0,%1,%2,%3};" \
        : "+f"((C)[0]), "+f"((C)[1]), "+f"((C)[2]), "+f"((C)[3]) \
        : "r"((A)[0]), "r"((A)[1]), "r"((A)[2]), "r"((A)[3]), "r"(B0), "r"(B1))

__device__ __forceinline__ void f2h_split(float v, unsigned short& hi, unsigned short& lo) {
    __half h = __float2half_rn(v);
    hi = __half_as_ushort(h);
    lo = __half_as_ushort(__float2half_rn(v - __half2float(h)));
}

// ===================== static device scratch =====================
__device__ float g_base[Nn * HIDk];
__device__ float g_hb[Bb * HIDk];
__device__ float g_pk[Ee * HIDk];
__device__ float g_cgw[Dd];
__device__ float g_CgCb[2];
__device__ float g_logits[Nn * Ee];
__device__ int   g_cnt[Ee];
__device__ int   g_off[Ee];
__device__ int   g_rtoff[Ee + 1];   // rowtile prefix sums
__device__ int   g_tick[2];         // persistent-kernel tickets
__device__ int   g_te[Nn * 2];
__device__ int   g_tp[Nn * 2];
__device__ float g_tw[Nn * 2];
__device__ int   g_ptok[NP];
__device__ float g_pw[NP];
__device__ float g_Op[(size_t)NP * Dd];
// fp16 split storage
__device__ unsigned short g_xh[(size_t)Nn * Dd];
__device__ unsigned short g_xl[(size_t)Nn * Dd];
__device__ unsigned short g_WgH[(size_t)Ee * Ff * Dd];
__device__ unsigned short g_WuH[(size_t)Ee * Ff * Dd];
__device__ unsigned short g_WdH[(size_t)Ee * Dd * Ff];
__device__ unsigned short g_Hh[(size_t)NP * Ff];
__device__ unsigned short g_W2TH[(size_t)Dd * HIDk];
__device__ unsigned short g_W2TL[(size_t)Dd * HIDk];
__device__ unsigned short g_W1TH[(size_t)HIDk * Dd];
__device__ unsigned short g_W1TL[(size_t)HIDk * Dd];

// ===================== prep =====================
__global__ void prep_kernel(const float* __restrict__ hist, const float* __restrict__ W1h,
                            const float* __restrict__ b1,
                            const float* __restrict__ persona, const float* __restrict__ W1p,
                            const float* __restrict__ ln_g, const float* __restrict__ ln_b,
                            const float* __restrict__ Wg, const float* __restrict__ bg) {
    int bx = blockIdx.x, tid = threadIdx.x;
    if (bx < 4) {
        float acc = b1[tid];
        const float* hr = hist + bx * Hh;
        for (int k = 0; k < Hh; k++) acc += hr[k] * W1h[k * HIDk + tid];
        g_hb[bx * HIDk + tid] = acc;
    } else if (bx < 12) {
        int e = bx - 4;
        float acc = 0.f;
        const float* pr = persona + e * Dd;
        for (int k = 0; k < Dd; k++) acc += pr[k] * W1p[k * HIDk + tid];
        g_pk[e * HIDk + tid] = acc;
    } else {
        __shared__ float sg[128], sb[128];
        float a = 0.f, b = 0.f;
        for (int d = tid; d < Dd; d += 128) {
            float w = Wg[d];
            float c = ln_g[d] * w;
            g_cgw[d] = c;
            a += c;
            b += ln_b[d] * w;
        }
        sg[tid] = a; sb[tid] = b;
        __syncthreads();
        for (int s = 64; s > 0; s >>= 1) {
            if (tid < s) { sg[tid] += sg[tid + s]; sb[tid] += sb[tid + s]; }
            __syncthreads();
        }
        if (tid == 0) { g_CgCb[0] = sg[0]; g_CgCb[1] = sb[0] + bg[0]; }
    }
}

// ===================== W2 -> W2^T fp16 hi/lo =====================
__global__ void w2t_kernel(const float* __restrict__ W2) {
    __shared__ float T[32][33];
    int d0 = blockIdx.x * 32, k0 = blockIdx.y * 32;
    int tid = threadIdx.x;
#pragma unroll
    for (int i = 0; i < 4; i++) {
        int kk = (tid >> 5) + i * 8, dd = tid & 31;
        T[kk][dd] = W2[(size_t)(k0 + kk) * Dd + d0 + dd];
    }
    __syncthreads();
#pragma unroll
    for (int i = 0; i < 4; i++) {
        int dd = (tid >> 5) + i * 8, kk = tid & 31;
        unsigned short hi, lo;
        f2h_split(T[kk][dd], hi, lo);
        g_W2TH[(size_t)(d0 + dd) * HIDk + k0 + kk] = hi;
        g_W2TL[(size_t)(d0 + dd) * HIDk + k0 + kk] = lo;
    }
}

// ===================== W1x -> W1x^T fp16 hi/lo =====================
__global__ void w1t_kernel(const float* __restrict__ W1x) {
    __shared__ float T[32][33];
    int k0 = blockIdx.x * 32, d0 = blockIdx.y * 32;
    int tid = threadIdx.x;
#pragma unroll
    for (int i = 0; i < 4; i++) {
        int dd = (tid >> 5) + i * 8, kk = tid & 31;
        T[dd][kk] = W1x[(size_t)(d0 + dd) * HIDk + k0 + kk];
    }
    __syncthreads();
#pragma unroll
    for (int i = 0; i < 4; i++) {
        int kk = (tid >> 5) + i * 8, dd = tid & 31;
        unsigned short hi, lo;
        f2h_split(T[dd][kk], hi, lo);
        g_W1TH[(size_t)(k0 + kk) * Dd + d0 + dd] = hi;
        g_W1TL[(size_t)(k0 + kk) * Dd + d0 + dd] = lo;
    }
}

// ===================== x -> fp16 hi/lo =====================
__global__ void xconv_kernel(const float* __restrict__ x) {
    size_t i = (size_t)blockIdx.x * 256 + threadIdx.x;
    float4 v = ((const float4*)x)[i];
    unsigned short h0, l0, h1, l1, h2, l2, h3, l3;
    f2h_split(v.x, h0, l0); f2h_split(v.y, h1, l1);
    f2h_split(v.z, h2, l2); f2h_split(v.w, h3, l3);
    uint2 ph = make_uint2((uint32_t)h0 | ((uint32_t)h1 << 16), (uint32_t)h2 | ((uint32_t)h3 << 16));
    uint2 pl = make_uint2((uint32_t)l0 | ((uint32_t)l1 << 16), (uint32_t)l2 | ((uint32_t)l3 << 16));
    *(uint2*)(g_xh + i * 4) = ph;
    *(uint2*)(g_xl + i * 4) = pl;
}

// ===================== base = x @ W1x + hb (tensor-core, 3-term) =====================
#define BM_STAGE 30720
#define BM_SMEM (3 * BM_STAGE)

__global__ __launch_bounds__(256, 2) void base_mma() {
    extern __shared__ char sm[];
    int n0 = blockIdx.x * 64;
    int tid = threadIdx.x, lane = tid & 31, wid = tid >> 5;
    int wy = wid & 1, wx = wid >> 1;
    uint32_t sb0 = smem_u32(sm);

    uint32_t sdst[6];
    const char* gsrc[6];
    int isB[6];
#pragma unroll
    for (int j = 0; j < 6; j++) {
        int sid = tid + 256 * j;
        const unsigned short* g;
        uint32_t so;
        int b = 0;
        if (sid < 256) {
            int row = sid >> 2, seg = sid & 3;
            so = row * 80u + seg * 16u;
            g = g_xh + (size_t)(n0 + row) * Dd + seg * 8;
        } else if (sid < 512) {
            int rid = sid - 256;
            int row = rid >> 2, seg = rid & 3;
            so = 5120u + row * 80u + seg * 16u;
            g = g_xl + (size_t)(n0 + row) * Dd + seg * 8;
        } else if (sid < 1024) {
            int rid = sid - 512;
            int row = rid >> 2, seg = rid & 3;
            so = 10240u + row * 80u + seg * 16u;
            g = g_W1TH + (size_t)row * Dd + seg * 8;
            b = 1;
        } else {
            int rid = sid - 1024;
            int row = rid >> 2, seg = rid & 3;
            so = 20480u + row * 80u + seg * 16u;
            g = g_W1TL + (size_t)row * Dd + seg * 8;
            b = 1;
        }
        sdst[j] = so;
        gsrc[j] = (const char*)g;
        isB[j] = b;
    }

    float acc[2][4][4];
#pragma unroll
    for (int a = 0; a < 2; a++)
#pragma unroll
        for (int b = 0; b < 4; b++)
#pragma unroll
            for (int c = 0; c < 4; c++) acc[a][b][c] = 0.f;

    uint32_t aoff = (uint32_t)((wy * 32 + (lane & 15)) * 80 + (lane >> 4) * 16);
    uint32_t boff = (uint32_t)((wx * 32 + ((lane & 7) | ((lane >> 4) << 3))) * 80 + ((lane >> 3) & 1) * 16);

    const int NCH = 32;
#pragma unroll
    for (int j = 0; j < 6; j++) {
        if (isB[j]) { CPASYNC16_CA(sb0 + sdst[j], gsrc[j]); }
        else        { CPASYNC16(sb0 + sdst[j], gsrc[j]); }
    }
    CP_COMMIT();
#pragma unroll
    for (int j = 0; j < 6; j++) {
        if (isB[j]) { CPASYNC16_CA(sb0 + BM_STAGE + sdst[j], gsrc[j] + 64); }
        else        { CPASYNC16(sb0 + BM_STAGE + sdst[j], gsrc[j] + 64); }
    }
    CP_COMMIT();

    for (int ch = 0; ch < NCH; ch++) {
        if (ch == NCH - 1) { CP_WAIT(0); } else { CP_WAIT(1); }
        __syncthreads();
        if (ch + 2 < NCH) {
            uint32_t stg = sb0 + ((ch + 2) % 3) * BM_STAGE;
            int cb = (ch + 2) * 64;
#pragma unroll
            for (int j = 0; j < 6; j++) {
                if (isB[j]) { CPASYNC16_CA(stg + sdst[j], gsrc[j] + cb); }
                else        { CPASYNC16(stg + sdst[j], gsrc[j] + cb); }
            }
            CP_COMMIT();
        }
        uint32_t s = sb0 + (ch % 3) * BM_STAGE;
#pragma unroll
        for (int k16 = 0; k16 < 2; k16++) {
            uint32_t kb = k16 * 32;
            uint32_t ah[2][4], al[2][4], bh[2][4], bl[2][4];
#pragma unroll
            for (int mt = 0; mt < 2; mt++) {
                LDSM4(ah[mt], s + aoff + mt * (16 * 80) + kb);
                LDSM4(al[mt], s + 5120 + aoff + mt * (16 * 80) + kb);
            }
#pragma unroll
            for (int nt = 0; nt < 2; nt++) {
                LDSM4(bh[nt], s + 10240 + boff + nt * (16 * 80) + kb);
                LDSM4(bl[nt], s + 20480 + boff + nt * (16 * 80) + kb);
            }
#pragma unroll
            for (int mt = 0; mt < 2; mt++)
#pragma unroll
                for (int nt = 0; nt < 2; nt++)
#pragma unroll
                    for (int h = 0; h < 2; h++) {
                        MMA16816(acc[mt][nt * 2 + h], ah[mt], bh[nt][2 * h], bh[nt][2 * h + 1]);
                        MMA16816(acc[mt][nt * 2 + h], ah[mt], bl[nt][2 * h], bl[nt][2 * h + 1]);
                        MMA16816(acc[mt][nt * 2 + h], al[mt], bh[nt][2 * h], bh[nt][2 * h + 1]);
                    }
        }
    }

#pragma unroll
    for (int mt = 0; mt < 2; mt++)
#pragma unroll
        for (int rh = 0; rh < 2; rh++) {
            int row = n0 + wy * 32 + mt * 16 + (lane >> 2) + rh * 8;
            const float* hb = g_hb + (row >> 11) * HIDk;
#pragma unroll
            for (int nq = 0; nq < 4; nq++) {
                int col = wx * 32 + nq * 8 + (lane & 3) * 2;
                g_base[(size_t)row * HIDk + col]     = acc[mt][nq][rh * 2]     + hb[col];
                g_base[(size_t)row * HIDk + col + 1] = acc[mt][nq][rh * 2 + 1] + hb[col + 1];
            }
        }
}

// ===================== merge: W' = W + A@B -> transposed fp16 hi =====================
__global__ __launch_bounds__(256) void merge_kernel(
    const float* __restrict__ Wgate, const float* __restrict__ Wup, const float* __restrict__ Wdown,
    const float* __restrict__ Ag, const float* __restrict__ Bg,
    const float* __restrict__ Au, const float* __restrict__ Bu,
    const float* __restrict__ Ad, const float* __restrict__ Bd) {
    __shared__ float As[128][17];
    __shared__ float Bs[16][65];
    __shared__ unsigned short Thi[64][136];
    int e = blockIdx.y, t = blockIdx.x, tid = threadIdx.x;
    const float *src, *Ap, *Bp;
    unsigned short *dhi;
    int r0, c0, rowStride, outStride;
    if (t < 352) {
        int kt = t / 44, ft = t % 44;
        r0 = kt * 128; c0 = ft * 64; rowStride = Ff; outStride = Dd;
        src = Wgate + (size_t)e * Dd * Ff; Ap = Ag + (size_t)e * Dd * Rr; Bp = Bg + (size_t)e * Rr * Ff;
        dhi = g_WgH + (size_t)e * Ff * Dd;
    } else if (t < 704) {
        t -= 352;
        int kt = t / 44, ft = t % 44;
        r0 = kt * 128; c0 = ft * 64; rowStride = Ff; outStride = Dd;
        src = Wup + (size_t)e * Dd * Ff; Ap = Au + (size_t)e * Dd * Rr; Bp = Bu + (size_t)e * Rr * Ff;
        dhi = g_WuH + (size_t)e * Ff * Dd;
    } else {
        t -= 704;
        int kt = t / 16, ft = t % 16;
        r0 = kt * 128; c0 = ft * 64; rowStride = Dd; outStride = Ff;
        src = Wdown + (size_t)e * Ff * Dd; Ap = Ad + (size_t)e * Ff * Rr; Bp = Bd + (size_t)e * Rr * Dd;
        dhi = g_WdH + (size_t)e * Dd * Ff;
    }
    {
        int r = tid >> 1, k0 = (tid & 1) * 8;
#pragma unroll
        for (int kk = 0; kk < 8; kk++)
            As[r][k0 + kk] = Ap[(size_t)(r0 + r) * Rr + k0 + kk];
    }
    for (int i = tid; i < 1024; i += 256) {
        int k = i >> 6, c = i & 63;
        Bs[k][c] = Bp[(size_t)k * rowStride + c0 + c];
    }
    __syncthreads();
    {
        int c = tid & 63, rb = tid >> 6;
        float vbuf[32];
        for (int rr = 0; rr < 32; rr++) {
            int r = rb * 32 + rr;
            float v = src[(size_t)(r0 + r) * rowStride + c0 + c];
#pragma unroll
            for (int k = 0; k < 16; k++) v += As[r][k] * Bs[k][c];
            vbuf[rr] = v;
        }
        for (int w = 0; w < 32; w++) {
            int rr = (w + c) & 31;
            Thi[c][rb * 32 + rr] = __half_as_ushort(__float2half_rn(vbuf[rr]));
        }
    }
    __syncthreads();
    {
        int c = tid >> 2, qq = tid & 3;
        const uint4* sh = (const uint4*)&Thi[c][qq * 32];
        uint4* dH = (uint4*)(dhi + (size_t)(c0 + c) * outStride + r0 + qq * 32);
#pragma unroll
        for (int m = 0; m < 4; m++) dH[m] = sh[m];
    }
}

// ===================== fused gate logits: 64 tokens x 2 experts per CTA =====================
#define L2_B0   69632
#define L2_BSTG 34816
#define L2_RED  (L2_B0 + 2 * L2_BSTG)
#define L2_B2   (L2_RED + 1536)
#define L2_CG   (L2_B2 + 4096)
#define L2_SMEM (L2_CG + 4096)

__global__ __launch_bounds__(256) void logits_kernel(const float* __restrict__ b2) {
    extern __shared__ char sm[];
    uint32_t sb = smem_u32(sm);
    int e0 = blockIdx.y * 2, n0 = blockIdx.x * 64;
    int tid = threadIdx.x, lane = tid & 31, wid = tid >> 5;
    int wy = wid & 3, wx = wid >> 2;

    {
        float* red = (float*)(sm + L2_RED);
        red[tid] = 0.f;
        if (tid < 128) red[tid + 256] = 0.f;
    }
#pragma unroll
    for (int i = 0; i < 4; i++) {
        ((float*)(sm + L2_B2))[tid + 256 * i] = b2[tid + 256 * i];
        ((float*)(sm + L2_CG))[tid + 256 * i] = g_cgw[tid + 256 * i];
    }
    {
        int t = tid >> 2, kq = (tid & 3) * 32;
        const float4* bp = (const float4*)(g_base + (size_t)(n0 + t) * HIDk + kq);
        const float4* p0 = (const float4*)(g_pk + e0 * HIDk + kq);
        const float4* p1 = (const float4*)(g_pk + (e0 + 1) * HIDk + kq);
        unsigned short* ah0 = (unsigned short*)(sm)          + t * 136 + kq;
        unsigned short* al0 = (unsigned short*)(sm + 17408)  + t * 136 + kq;
        unsigned short* ah1 = (unsigned short*)(sm + 34816)  + t * 136 + kq;
        unsigned short* al1 = (unsigned short*)(sm + 52224)  + t * 136 + kq;
#pragma unroll
        for (int q = 0; q < 8; q++) {
            float4 a = bp[q];
            float4 pa = p0[q], pb = p1[q];
            float v0[4] = {fmaxf(a.x + pa.x, 0.f), fmaxf(a.y + pa.y, 0.f),
                           fmaxf(a.z + pa.z, 0.f), fmaxf(a.w + pa.w, 0.f)};
            float v1[4] = {fmaxf(a.x + pb.x, 0.f), fmaxf(a.y + pb.y, 0.f),
                           fmaxf(a.z + pb.z, 0.f), fmaxf(a.w + pb.w, 0.f)};
#pragma unroll
            for (int c = 0; c < 4; c++) {
                unsigned short hi, lo;
                f2h_split(v0[c], hi, lo);
                ah0[q * 4 + c] = hi; al0[q * 4 + c] = lo;
                f2h_split(v1[c], hi, lo);
                ah1[q * 4 + c] = hi; al1[q * 4 + c] = lo;
            }
        }
    }
    uint32_t sdst[8];
    uint32_t gofs[8];
    int ghl[8];
#pragma unroll
    for (int j = 0; j < 8; j++) {
        int sid = tid + 256 * j;
        int hl = sid >> 10;
        int rid = sid & 1023;
        int row = rid >> 4, seg = rid & 15;
        sdst[j] = (uint32_t)(hl * 17408 + row * 272 + seg * 16);
        gofs[j] = (uint32_t)(row * HIDk + seg * 8);
        ghl[j] = hl;
    }
#pragma unroll
    for (int j = 0; j < 8; j++) {
        const unsigned short* g = (ghl[j] ? g_W2TL : g_W2TH) + gofs[j];
        CPASYNC16_CA(sb + L2_B0 + sdst[j], (const char*)g);
    }
    CP_COMMIT();
    __syncthreads();

    float s1[2][2] = {{0.f,0.f},{0.f,0.f}}, s2v[2][2] = {{0.f,0.f},{0.f,0.f}}, s3[2][2] = {{0.f,0.f},{0.f,0.f}};
    uint32_t aoff = (uint32_t)((wy * 16 + (lane & 15)) * 272 + (lane >> 4) * 16);
    uint32_t boff = (uint32_t)(((wx * 32 + ((lane & 7) | ((lane >> 4) << 3))) * 272) + ((lane >> 3) & 1) * 16);

    for (int ch = 0; ch < 16; ch++) {
        if (ch + 1 < 16) {
            uint32_t stg = sb + L2_B0 + ((ch + 1) & 1) * L2_BSTG;
            uint32_t dadd = (uint32_t)((ch + 1) * 64 * HIDk);
#pragma unroll
            for (int j = 0; j < 8; j++) {
                const unsigned short* g = (ghl[j] ? g_W2TL : g_W2TH) + gofs[j] + dadd;
                CPASYNC16_CA(stg + sdst[j], (const char*)g);
            }
            CP_COMMIT();
            CP_WAIT(1);
        } else {
            CP_WAIT(0);
        }
        __syncthreads();
        uint32_t sB = sb + L2_B0 + (ch & 1) * L2_BSTG;
        float acc[2][4][4];
#pragma unroll
        for (int e = 0; e < 2; e++)
#pragma unroll
            for (int a = 0; a < 4; a++)
#pragma unroll
                for (int c = 0; c < 4; c++) acc[e][a][c] = 0.f;
#pragma unroll
        for (int k16 = 0; k16 < 8; k16++) {
            uint32_t kb = (uint32_t)(k16 * 32);
            uint32_t bh[2][4], bl[2][4];
            LDSM4(bh[0], sB + boff + kb);
            LDSM4(bh[1], sB + boff + 16 * 272 + kb);
            LDSM4(bl[0], sB + 17408 + boff + kb);
            LDSM4(bl[1], sB + 17408 + boff + 16 * 272 + kb);
#pragma unroll
            for (int e = 0; e < 2; e++) {
                uint32_t ahr[4], alr[4];
                LDSM4(ahr, sb + e * 34816 + aoff + kb);
                LDSM4(alr, sb + e * 34816 + 17408 + aoff + kb);
#pragma unroll
                for (int nt = 0; nt < 2; nt++)
#pragma unroll
                    for (int h = 0; h < 2; h++) {
                        MMA16816(acc[e][nt * 2 + h], ahr, bh[nt][2 * h], bh[nt][2 * h + 1]);
                        MMA16816(acc[e][nt * 2 + h], alr, bh[nt][2 * h], bh[nt][2 * h + 1]);
                        MMA16816(acc[e][nt * 2 + h], ahr, bl[nt][2 * h], bl[nt][2 * h + 1]);
                    }
            }
        }
#pragma unroll
        for (int e = 0; e < 2; e++)
#pragma unroll
            for (int nt4 = 0; nt4 < 4; nt4++) {
                int col = ch * 64 + wx * 32 + nt4 * 8 + (lane & 3) * 2;
                float b0 = ((float*)(sm + L2_B2))[col], b1v = ((float*)(sm + L2_B2))[col + 1];
                float c0 = ((float*)(sm + L2_CG))[col], c1v = ((float*)(sm + L2_CG))[col + 1];
                float f;
                f = fmaxf(acc[e][nt4][0] + b0, 0.f);  s1[e][0] += f * c0;  s2v[e][0] += f; s3[e][0] += f * f;
                f = fmaxf(acc[e][nt4][1] + b1v, 0.f); s1[e][0] += f * c1v; s2v[e][0] += f; s3[e][0] += f * f;
                f = fmaxf(acc[e][nt4][2] + b0, 0.f);  s1[e][1] += f * c0;  s2v[e][1] += f; s3[e][1] += f * f;
                f = fmaxf(acc[e][nt4][3] + b1v, 0.f); s1[e][1] += f * c1v; s2v[e][1] += f; s3[e][1] += f * f;
            }
        __syncthreads();
    }
#pragma unroll
    for (int off = 1; off <= 2; off <<= 1) {
#pragma unroll
        for (int e = 0; e < 2; e++)
#pragma unroll
            for (int i = 0; i < 2; i++) {
                s1[e][i]  += __shfl_xor_sync(0xffffffffu, s1[e][i], off);
                s2v[e][i] += __shfl_xor_sync(0xffffffffu, s2v[e][i], off);
                s3[e][i]  += __shfl_xor_sync(0xffffffffu, s3[e][i], off);
            }
    }
    if ((lane & 3) == 0) {
        int row = wy * 16 + (lane >> 2);
        float* red = (float*)(sm + L2_RED);
#pragma unroll
        for (int e = 0; e < 2; e++) {
            atomicAdd(&red[e * 192 + row],           s1[e][0]);
            atomicAdd(&red[e * 192 + row + 8],       s1[e][1]);
            atomicAdd(&red[e * 192 + 64 + row],      s2v[e][0]);
            atomicAdd(&red[e * 192 + 64 + row + 8],  s2v[e][1]);
            atomicAdd(&red[e * 192 + 128 + row],     s3[e][0]);
            atomicAdd(&red[e * 192 + 128 + row + 8], s3[e][1]);
        }
    }
    __syncthreads();
    if (tid < 128) {
        int e = tid >> 6, t = tid & 63;
        float* red = (float*)(sm + L2_RED);
        float S1 = red[e * 192 + t], S2 = red[e * 192 + 64 + t], S3 = red[e * 192 + 128 + t];
        float Cg = g_CgCb[0], Cb = g_CgCb[1];
        float mu = S2 * (1.f / (float)Dd);
        float var = S3 * (1.f / (float)Dd) - mu * mu;
        float rstd = rsqrtf(var + LN_EPS);
        g_logits[(size_t)(n0 + t) * Ee + e0 + e] = rstd * (S1 - mu * Cg) + Cb;
    }
}

// ===================== routing =====================
__global__ void route_kernel() {
    int n = blockIdx.x * 256 + threadIdx.x;
    float l[Ee];
    float m = -1e30f;
#pragma unroll
    for (int e = 0; e < Ee; e++) { l[e] = g_logits[(size_t)n * Ee + e]; m = fmaxf(m, l[e]); }
    float s = 0.f;
#pragma unroll
    for (int e = 0; e < Ee; e++) { l[e] = expf(l[e] - m); s += l[e]; }
    float inv = 1.f / s;
#pragma unroll
    for (int e = 0; e < Ee; e++) l[e] *= inv;
    int i0 = 0; float b0 = l[0];
#pragma unroll
    for (int e = 1; e < Ee; e++) if (l[e] > b0) { b0 = l[e]; i0 = e; }
    int i1 = -1; float b1 = -1.f;
#pragma unroll
    for (int e = 0; e < Ee; e++) if (e != i0 && l[e] > b1) { b1 = l[e]; i1 = e; }
    int p0 = atomicAdd(&g_cnt[i0], 1);
    int p1 = atomicAdd(&g_cnt[i1], 1);
    g_te[2 * n] = i0; g_tp[2 * n] = p0; g_tw[2 * n] = b0;
    g_te[2 * n + 1] = i1; g_tp[2 * n + 1] = p1; g_tw[2 * n + 1] = b1;
}

// scatter + scan + rowtile prefix
__global__ void scatter_kernel() {
    __shared__ int soff[Ee];
    if (threadIdx.x == 0) {
        int a = 0;
        for (int e = 0; e < Ee; e++) { soff[e] = a; a += g_cnt[e]; }
        if (blockIdx.x == 0) {
            int rt = 0;
            for (int e = 0; e < Ee; e++) {
                g_off[e] = soff[e];
                g_rtoff[e] = rt;
                rt += (g_cnt[e] + 127) >> 7;
            }
            g_rtoff[Ee] = rt;
        }
    }
    __syncthreads();
    int n = blockIdx.x * 256 + threadIdx.x;
#pragma unroll
    for (int i = 0; i < 2; i++) {
        int slot = soff[g_te[2 * n + i]] + g_tp[2 * n + i];
        g_ptok[slot] = n;
        g_pw[slot] = g_tw[2 * n + i];
    }
}

// ===================== expert GEMM1 (persistent tickets; 128 tok x 64 f gate+up; 4-stage) =====================
#define G1_STAGE 20480
#define G1_SMEM (1024 + 4 * G1_STAGE)

__global__ __launch_bounds__(256, 2) void moe_gemm1() {
    extern __shared__ char sm[];
    __shared__ int s_tile;
    int tid = threadIdx.x, lane = tid & 31, wid = tid >> 5;
    int wy = wid & 3, wx = wid >> 2;
    uint32_t sb0 = smem_u32(sm) + 1024;
    uint32_t aoff = (uint32_t)((wy * 32 + (lane & 15)) * 80 + (lane >> 4) * 16);
    uint32_t boff = (uint32_t)((wx * 32 + ((lane & 7) | ((lane >> 4) << 3))) * 80 + ((lane >> 3) & 1) * 16);
    const int NCH = 32;
    int tot = g_rtoff[Ee] * 44;

    for (;;) {
        if (tid == 0) s_tile = atomicAdd(&g_tick[0], 1);
        __syncthreads();
        int t = s_tile;
        if (t >= tot) break;
        int rg = t / 44, ftile = t % 44;
        int e = 0;
#pragma unroll
        for (int q = 1; q < Ee; q++) if (g_rtoff[q] <= rg) e = q;
        int r0 = (rg - g_rtoff[e]) * 128;
        int cnt = g_cnt[e], off = g_off[e];
        int f0 = ftile * 64;

        int* stok = (int*)sm;
        if (tid < 128) {
            int lr = r0 + tid; if (lr >= cnt) lr = cnt - 1;
            stok[tid] = g_ptok[off + lr];
        }
        __syncthreads();

        uint32_t sdst[4];
        const char* gsrc[4];
        int isA[4];
#pragma unroll
        for (int j = 0; j < 4; j++) {
            int sid = tid + 256 * j;
            int region = sid >> 9;
            int rid = sid & 511;
            int row = rid >> 2, seg = rid & 3;
            sdst[j] = (uint32_t)(region * 10240 + row * 80 + seg * 16);
            const unsigned short* g;
            if (region == 0) g = g_xh + (size_t)stok[row] * Dd;
            else             g = (row < 64) ? g_WgH + ((size_t)e * Ff + f0 + row) * Dd
                                            : g_WuH + ((size_t)e * Ff + f0 + row - 64) * Dd;
            gsrc[j] = (const char*)(g + seg * 8);
            isA[j] = (region == 0);
        }

        float accG[2][4][4], accU[2][4][4];
#pragma unroll
        for (int a = 0; a < 2; a++)
#pragma unroll
            for (int b = 0; b < 4; b++)
#pragma unroll
                for (int c = 0; c < 4; c++) { accG[a][b][c] = 0.f; accU[a][b][c] = 0.f; }

#pragma unroll
        for (int p = 0; p < 3; p++) {
#pragma unroll
            for (int j = 0; j < 4; j++) {
                if (isA[j]) { CPASYNC16_CA(sb0 + p * G1_STAGE + sdst[j], gsrc[j] + p * 64); }
                else        { CPASYNC16(sb0 + p * G1_STAGE + sdst[j], gsrc[j] + p * 64); }
            }
            CP_COMMIT();
        }

        for (int ch = 0; ch < NCH; ch++) {
            if (ch >= NCH - 3) { CP_WAIT(0); } else { CP_WAIT(2); }
            __syncthreads();
            if (ch + 3 < NCH) {
                uint32_t stg = sb0 + ((ch + 3) & 3) * G1_STAGE;
                int cb = (ch + 3) * 64;
#pragma unroll
                for (int j = 0; j < 4; j++) {
                    if (isA[j]) { CPASYNC16_CA(stg + sdst[j], gsrc[j] + cb); }
                    else        { CPASYNC16(stg + sdst[j], gsrc[j] + cb); }
                }
                CP_COMMIT();
            }
            uint32_t s = sb0 + (ch & 3) * G1_STAGE;
#pragma unroll
            for (int k16 = 0; k16 < 2; k16++) {
                uint32_t kb = k16 * 32;
                uint32_t ah[2][4], bg[2][4], bu[2][4];
#pragma unroll
                for (int mt = 0; mt < 2; mt++)
                    LDSM4(ah[mt], s + aoff + mt * (16 * 80) + kb);
#pragma unroll
                for (int nt = 0; nt < 2; nt++) {
                    LDSM4(bg[nt], s + 10240 + boff + nt * (16 * 80) + kb);
                    LDSM4(bu[nt], s + 10240 + 5120 + boff + nt * (16 * 80) + kb);
                }
#pragma unroll
                for (int mt = 0; mt < 2; mt++)
#pragma unroll
                    for (int nt = 0; nt < 2; nt++)
#pragma unroll
                        for (int h = 0; h < 2; h++) {
                            MMA16816(accG[mt][nt * 2 + h], ah[mt], bg[nt][2 * h], bg[nt][2 * h + 1]);
                            MMA16816(accU[mt][nt * 2 + h], ah[mt], bu[nt][2 * h], bu[nt][2 * h + 1]);
                        }
            }
        }

#pragma unroll
        for (int mt = 0; mt < 2; mt++)
#pragma unroll
            for (int rh = 0; rh < 2; rh++) {
                int lr = wy * 32 + mt * 16 + (lane >> 2) + rh * 8;
                if (r0 + lr < cnt) {
                    int slot = off + r0 + lr;
#pragma unroll
                    for (int nt8 = 0; nt8 < 4; nt8++) {
                        int col = f0 + wx * 32 + nt8 * 8 + (lane & 3) * 2;
                        float g0 = accG[mt][nt8][rh * 2 + 0], g1 = accG[mt][nt8][rh * 2 + 1];
                        float u0 = accU[mt][nt8][rh * 2 + 0], u1 = accU[mt][nt8][rh * 2 + 1];
                        float h0 = g0 / (1.f + __expf(-g0)) * u0;
                        float h1 = g1 / (1.f + __expf(-g1)) * u1;
                        unsigned short a0 = __half_as_ushort(__float2half_rn(h0));
                        unsigned short a1 = __half_as_ushort(__float2half_rn(h1));
                        size_t idx = ((size_t)slot * Ff + col) >> 1;
                        ((uint32_t*)g_Hh)[idx] = (uint32_t)a0 | ((uint32_t)a1 << 16);
                    }
                }
            }
        __syncthreads();
    }
}

// ===================== expert GEMM2 (persistent tickets; 128x128; 4-stage) =====================
#define G2_STAGE 20480
#define G2_SMEM (4 * G2_STAGE)

__global__ __launch_bounds__(256, 2) void moe_gemm2() {
    extern __shared__ char sm[];
    __shared__ int s_tile;
    int tid = threadIdx.x, lane = tid & 31, wid = tid >> 5;
    int wy = wid & 3, wx = wid >> 2;
    uint32_t sb0 = smem_u32(sm);
    uint32_t aoff = (uint32_t)((wy * 32 + (lane & 15)) * 80 + (lane >> 4) * 16);
    uint32_t boff = (uint32_t)((wx * 64 + ((lane & 7) | ((lane >> 4) << 3))) * 80 + ((lane >> 3) & 1) * 16);
    const int NCH = 88;
    int tot = g_rtoff[Ee] * 8;

    for (;;) {
        if (tid == 0) s_tile = atomicAdd(&g_tick[1], 1);
        __syncthreads();
        int t = s_tile;
        if (t >= tot) break;
        int rg = t >> 3, dtile = t & 7;
        int e = 0;
#pragma unroll
        for (int q = 1; q < Ee; q++) if (g_rtoff[q] <= rg) e = q;
        int r0 = (rg - g_rtoff[e]) * 128;
        int cnt = g_cnt[e], off = g_off[e];
        int d0 = dtile * 128;

        uint32_t sdst[4];
        const char* gsrc[4];
        int isA[4];
#pragma unroll
        for (int j = 0; j < 4; j++) {
            int sid = tid + 256 * j;
            const unsigned short* g;
            uint32_t so;
            int a = 0;
            if (sid < 512) {
                int row = sid >> 2, seg = sid & 3;
                so = row * 80u + seg * 16u;
                int lr = r0 + row; if (lr >= cnt) lr = cnt - 1;
                g = g_Hh + (size_t)(off + lr) * Ff + seg * 8;
                a = 1;
            } else {
                int rid = sid - 512;
                int row = rid >> 2, seg = rid & 3;
                so = 10240u + row * 80u + seg * 16u;
                g = g_WdH + ((size_t)e * Dd + d0 + row) * Ff + seg * 8;
            }
            sdst[j] = so;
            gsrc[j] = (const char*)g;
            isA[j] = a;
        }

        float acc[2][8][4];
#pragma unroll
        for (int a = 0; a < 2; a++)
#pragma unroll
            for (int b = 0; b < 8; b++)
#pragma unroll
                for (int c = 0; c < 4; c++) acc[a][b][c] = 0.f;

#pragma unroll
        for (int p = 0; p < 3; p++) {
#pragma unroll
            for (int j = 0; j < 4; j++) {
                if (isA[j]) { CPASYNC16_CA(sb0 + p * G2_STAGE + sdst[j], gsrc[j] + p * 64); }
                else        { CPASYNC16(sb0 + p * G2_STAGE + sdst[j], gsrc[j] + p * 64); }
            }
            CP_COMMIT();
        }

        for (int ch = 0; ch < NCH; ch++) {
            if (ch >= NCH - 3) { CP_WAIT(0); } else { CP_WAIT(2); }
            __syncthreads();
            if (ch + 3 < NCH) {
                uint32_t stg = sb0 + ((ch + 3) & 3) * G2_STAGE;
                int cb = (ch + 3) * 64;
#pragma unroll
                for (int j = 0; j < 4; j++) {
                    if (isA[j]) { CPASYNC16_CA(stg + sdst[j], gsrc[j] + cb); }
                    else        { CPASYNC16(stg + sdst[j], gsrc[j] + cb); }
                }
                CP_COMMIT();
            }
            uint32_t s = sb0 + (ch & 3) * G2_STAGE;
#pragma unroll
            for (int k16 = 0; k16 < 2; k16++) {
                uint32_t kb = k16 * 32;
                uint32_t ah[2][4], bf[4][4];
#pragma unroll
                for (int mt = 0; mt < 2; mt++)
                    LDSM4(ah[mt], s + aoff + mt * (16 * 80) + kb);
#pragma unroll
                for (int nt = 0; nt < 4; nt++) LDSM4(bf[nt], s + 10240 + boff + nt * (16 * 80) + kb);
#pragma unroll
                for (int mt = 0; mt < 2; mt++)
#pragma unroll
                    for (int nt = 0; nt < 4; nt++)
#pragma unroll
                        for (int h = 0; h < 2; h++)
                            MMA16816(acc[mt][nt * 2 + h], ah[mt], bf[nt][2 * h], bf[nt][2 * h + 1]);
            }
        }

#pragma unroll
        for (int mt = 0; mt < 2; mt++)
#pragma unroll
            for (int rh = 0; rh < 2; rh++) {
                int lr = wy * 32 + mt * 16 + (lane >> 2) + rh * 8;
                if (r0 + lr < cnt) {
                    int slot = off + r0 + lr;
                    float w = g_pw[slot];
                    float* op = g_Op + (size_t)slot * Dd + d0 + wx * 64 + (lane & 3) * 2;
#pragma unroll
                    for (int nt8 = 0; nt8 < 8; nt8++) {
                        float2 v = make_float2(acc[mt][nt8][rh * 2 + 0] * w,
                                               acc[mt][nt8][rh * 2 + 1] * w);
                        *(float2*)(op + nt8 * 8) = v;
                    }
                }
            }
        __syncthreads();
    }
}

// ===================== combine: out[tok] = Op[slot0] + Op[slot1] =====================
__global__ void combine_kernel(float* __restrict__ out) {
    size_t i = (size_t)blockIdx.x * 256 + threadIdx.x;
    int tok = (int)(i >> 8);
    int q = (int)(i & 255);
    int s0 = g_off[g_te[2 * tok]]     + g_tp[2 * tok];
    int s1 = g_off[g_te[2 * tok + 1]] + g_tp[2 * tok + 1];
    float4 a = ((const float4*)(g_Op + (size_t)s0 * Dd))[q];
    float4 b = ((const float4*)(g_Op + (size_t)s1 * Dd))[q];
    float4 r = make_float4(a.x + b.x, a.y + b.y, a.z + b.z, a.w + b.w);
    ((float4*)(out + (size_t)tok * Dd))[q] = r;
}

// ===================== launch =====================
extern "C" void kernel_launch(void* const* d_in, const int* in_sizes, int n_in,
                              void* d_out, int out_size) {
    (void)in_sizes; (void)n_in; (void)out_size;
    const float* x       = (const float*)d_in[0];
    const float* hist    = (const float*)d_in[1];
    const float* persona = (const float*)d_in[2];
    const float* W1x     = (const float*)d_in[3];
    const float* W1h     = (const float*)d_in[4];
    const float* W1p     = (const float*)d_in[5];
    const float* b1      = (const float*)d_in[6];
    const float* W2      = (const float*)d_in[7];
    const float* b2      = (const float*)d_in[8];
    const float* ln_g    = (const float*)d_in[9];
    const float* ln_b    = (const float*)d_in[10];
    const float* Wg      = (const float*)d_in[11];
    const float* bg      = (const float*)d_in[12];
    const float* Wgate   = (const float*)d_in[13];
    const float* Wup     = (const float*)d_in[14];
    const float* Wdown   = (const float*)d_in[15];
    const float* Ag      = (const float*)d_in[16];
    const float* Bg      = (const float*)d_in[17];
    const float* Au      = (const float*)d_in[18];
    const float* Bu      = (const float*)d_in[19];
    const float* Ad      = (const float*)d_in[20];
    const float* Bd      = (const float*)d_in[21];
    float* out = (float*)d_out;

    static cudaStream_t s2 = nullptr;
    static cudaEvent_t evFork = nullptr, evJoin = nullptr;
    if (!s2) {
        cudaStreamCreateWithFlags(&s2, cudaStreamNonBlocking);
        cudaEventCreateWithFlags(&evFork, cudaEventDisableTiming);
        cudaEventCreateWithFlags(&evJoin, cudaEventDisableTiming);
    }

    cudaFuncSetAttribute(moe_gemm1, cudaFuncAttributeMaxDynamicSharedMemorySize, G1_SMEM);
    cudaFuncSetAttribute(moe_gemm2, cudaFuncAttributeMaxDynamicSharedMemorySize, G2_SMEM);
    cudaFuncSetAttribute(logits_kernel, cudaFuncAttributeMaxDynamicSharedMemorySize, L2_SMEM);
    cudaFuncSetAttribute(base_mma, cudaFuncAttributeMaxDynamicSharedMemorySize, BM_SMEM);

    void* cntp = nullptr;
    void* tickp = nullptr;
    cudaGetSymbolAddress(&cntp, g_cnt);
    cudaGetSymbolAddress(&tickp, g_tick);

    cudaMemsetAsync(cntp, 0, Ee * sizeof(int));
    cudaMemsetAsync(tickp, 0, 2 * sizeof(int));

    cudaEventRecord(evFork, 0);
    cudaStreamWaitEvent(s2, evFork, 0);
    merge_kernel<<<dim3(1056, Ee), 256, 0, s2>>>(Wgate, Wup, Wdown, Ag, Bg, Au, Bu, Ad, Bd);
    cudaEventRecord(evJoin, s2);

    prep_kernel<<<13, 128>>>(hist, W1h, b1, persona, W1p, ln_g, ln_b, Wg, bg);
    w2t_kernel<<<dim3(Dd / 32, HIDk / 32), 256>>>(W2);
    w1t_kernel<<<dim3(HIDk / 32, Dd / 32), 256>>>(W1x);
    xconv_kernel<<<(Nn * Dd) / 4 / 256, 256>>>(x);
    base_mma<<<Nn / 64, 256, BM_SMEM>>>();
    logits_kernel<<<dim3(Nn / 64, Ee / 2), 256, L2_SMEM>>>(b2);
    route_kernel<<<Nn / 256, 256>>>();
    scatter_kernel<<<Nn / 256, 256>>>();

    cudaStreamWaitEvent(0, evJoin, 0);
    moe_gemm1<<<296, 256, G1_SMEM>>>();
    moe_gemm2<<<296, 256, G2_SMEM>>>();
    combine_kernel<<<(Nn * Dd) / 4 / 256, 256>>>(out);
}

// round 17
// speedup vs baseline: 1.0219x; 1.0219x over previous
#include <cuda_runtime.h>
#include <cuda_fp16.h>
#include <math.h>
#include <stdint.h>

#define Bb 4
#define Ss 2048
#define Dd 1024
#define Hh 512
#define Ee 8
#define Ff 2816
#define Rr 16
#define HIDk 128
#define Nn 8192
#define NP 16384
#define LN_EPS 1e-5f

// ===================== baseline-PTX helpers =====================
__device__ __forceinline__ uint32_t smem_u32(const void* p) {
    uint32_t a;
    asm("{ .reg .u64 t; cvta.to.shared.u64 t, %1; cvt.u32.u64 %0, t; }" : "=r"(a) : "l"(p));
    return a;
}

#define CPASYNC16(dst, src) \
    asm volatile("cp.async.cg.shared.global [%0], [%1], 16;\n" :: "r"(dst), "l"(src))
#define CPASYNC16_CA(dst, src) \
    asm volatile("cp.async.ca.shared.global [%0], [%1], 16;\n" :: "r"(dst), "l"(src))
#define CP_COMMIT() asm volatile("cp.async.commit_group;\n" ::: "memory")
#define CP_WAIT(N)  asm volatile("cp.async.wait_group %0;\n" :: "n"(N) : "memory")

#define LDSM4(R, addr) \
    asm volatile("ldmatrix.sync.aligned.m8n8.x4.shared.b16 {%0,%1,%2,%3}, [%4];" \
        : "=r"((R)[0]), "=r"((R)[1]), "=r"((R)[2]), "=r"((R)[3]) : "r"(addr))

#define MMA16816(C, A, B0, B1) \
    asm volatile("mma.sync.aligned.m16n8k16.row.col.f32.f16.f16.f32 " \
        "{%0,%1,%2,%3}, {%4,%5,%6,%7}, {%8,%9}, {%0,%1,%2,%3};" \
        : "+f"((C)[0]), "+f"((C)[1]), "+f"((C)[2]), "+f"((C)[3]) \
        : "r"((A)[0]), "r"((A)[1]), "r"((A)[2]), "r"((A)[3]), "r"(B0), "r"(B1))

__device__ __forceinline__ void f2h_split(float v, unsigned short& hi, unsigned short& lo) {
    __half h = __float2half_rn(v);
    hi = __half_as_ushort(h);
    lo = __half_as_ushort(__float2half_rn(v - __half2float(h)));
}

// ===================== static device scratch =====================
__device__ float g_base[Nn * HIDk];
__device__ float g_hb[Bb * HIDk];
__device__ float g_pk[Ee * HIDk];
__device__ float g_cgw[Dd];
__device__ float g_CgCb[2];
__device__ float g_logits[Nn * Ee];
__device__ int   g_cnt[Ee];
__device__ int   g_off[Ee];
__device__ int   g_te[Nn * 2];
__device__ int   g_tp[Nn * 2];
__device__ float g_tw[Nn * 2];
__device__ int   g_ptok[NP];
__device__ float g_pw[NP];
__device__ float g_Op[(size_t)NP * Dd];
// fp16 split storage
__device__ unsigned short g_xh[(size_t)Nn * Dd];
__device__ unsigned short g_xl[(size_t)Nn * Dd];
__device__ unsigned short g_WgH[(size_t)Ee * Ff * Dd];
__device__ unsigned short g_WuH[(size_t)Ee * Ff * Dd];
__device__ unsigned short g_WdH[(size_t)Ee * Dd * Ff];
__device__ unsigned short g_Hh[(size_t)NP * Ff];
__device__ unsigned short g_W2TH[(size_t)Dd * HIDk];
__device__ unsigned short g_W2TL[(size_t)Dd * HIDk];
__device__ unsigned short g_W1TH[(size_t)HIDk * Dd];
__device__ unsigned short g_W1TL[(size_t)HIDk * Dd];

// ===================== prep =====================
__global__ void prep_kernel(const float* __restrict__ hist, const float* __restrict__ W1h,
                            const float* __restrict__ b1,
                            const float* __restrict__ persona, const float* __restrict__ W1p,
                            const float* __restrict__ ln_g, const float* __restrict__ ln_b,
                            const float* __restrict__ Wg, const float* __restrict__ bg) {
    int bx = blockIdx.x, tid = threadIdx.x;
    if (bx < 4) {
        float acc = b1[tid];
        const float* hr = hist + bx * Hh;
        for (int k = 0; k < Hh; k++) acc += hr[k] * W1h[k * HIDk + tid];
        g_hb[bx * HIDk + tid] = acc;
    } else if (bx < 12) {
        int e = bx - 4;
        float acc = 0.f;
        const float* pr = persona + e * Dd;
        for (int k = 0; k < Dd; k++) acc += pr[k] * W1p[k * HIDk + tid];
        g_pk[e * HIDk + tid] = acc;
    } else {
        __shared__ float sg[128], sb[128];
        float a = 0.f, b = 0.f;
        for (int d = tid; d < Dd; d += 128) {
            float w = Wg[d];
            float c = ln_g[d] * w;
            g_cgw[d] = c;
            a += c;
            b += ln_b[d] * w;
        }
        sg[tid] = a; sb[tid] = b;
        __syncthreads();
        for (int s = 64; s > 0; s >>= 1) {
            if (tid < s) { sg[tid] += sg[tid + s]; sb[tid] += sb[tid + s]; }
            __syncthreads();
        }
        if (tid == 0) { g_CgCb[0] = sg[0]; g_CgCb[1] = sb[0] + bg[0]; }
    }
}

// ===================== W2 -> W2^T fp16 hi/lo =====================
__global__ void w2t_kernel(const float* __restrict__ W2) {
    __shared__ float T[32][33];
    int d0 = blockIdx.x * 32, k0 = blockIdx.y * 32;
    int tid = threadIdx.x;
#pragma unroll
    for (int i = 0; i < 4; i++) {
        int kk = (tid >> 5) + i * 8, dd = tid & 31;
        T[kk][dd] = W2[(size_t)(k0 + kk) * Dd + d0 + dd];
    }
    __syncthreads();
#pragma unroll
    for (int i = 0; i < 4; i++) {
        int dd = (tid >> 5) + i * 8, kk = tid & 31;
        unsigned short hi, lo;
        f2h_split(T[kk][dd], hi, lo);
        g_W2TH[(size_t)(d0 + dd) * HIDk + k0 + kk] = hi;
        g_W2TL[(size_t)(d0 + dd) * HIDk + k0 + kk] = lo;
    }
}

// ===================== W1x -> W1x^T fp16 hi/lo =====================
__global__ void w1t_kernel(const float* __restrict__ W1x) {
    __shared__ float T[32][33];
    int k0 = blockIdx.x * 32, d0 = blockIdx.y * 32;
    int tid = threadIdx.x;
#pragma unroll
    for (int i = 0; i < 4; i++) {
        int dd = (tid >> 5) + i * 8, kk = tid & 31;
        T[dd][kk] = W1x[(size_t)(d0 + dd) * HIDk + k0 + kk];
    }
    __syncthreads();
#pragma unroll
    for (int i = 0; i < 4; i++) {
        int kk = (tid >> 5) + i * 8, dd = tid & 31;
        unsigned short hi, lo;
        f2h_split(T[dd][kk], hi, lo);
        g_W1TH[(size_t)(k0 + kk) * Dd + d0 + dd] = hi;
        g_W1TL[(size_t)(k0 + kk) * Dd + d0 + dd] = lo;
    }
}

// ===================== x -> fp16 hi/lo =====================
__global__ void xconv_kernel(const float* __restrict__ x) {
    size_t i = (size_t)blockIdx.x * 256 + threadIdx.x;
    float4 v = ((const float4*)x)[i];
    unsigned short h0, l0, h1, l1, h2, l2, h3, l3;
    f2h_split(v.x, h0, l0); f2h_split(v.y, h1, l1);
    f2h_split(v.z, h2, l2); f2h_split(v.w, h3, l3);
    uint2 ph = make_uint2((uint32_t)h0 | ((uint32_t)h1 << 16), (uint32_t)h2 | ((uint32_t)h3 << 16));
    uint2 pl = make_uint2((uint32_t)l0 | ((uint32_t)l1 << 16), (uint32_t)l2 | ((uint32_t)l3 << 16));
    *(uint2*)(g_xh + i * 4) = ph;
    *(uint2*)(g_xl + i * 4) = pl;
}

// ===================== base = x @ W1x + hb (tensor-core, 3-term) =====================
#define BM_STAGE 30720
#define BM_SMEM (3 * BM_STAGE)

__global__ __launch_bounds__(256, 2) void base_mma() {
    extern __shared__ char sm[];
    int n0 = blockIdx.x * 64;
    int tid = threadIdx.x, lane = tid & 31, wid = tid >> 5;
    int wy = wid & 1, wx = wid >> 1;
    uint32_t sb0 = smem_u32(sm);

    uint32_t sdst[6];
    const char* gsrc[6];
    int isB[6];
#pragma unroll
    for (int j = 0; j < 6; j++) {
        int sid = tid + 256 * j;
        const unsigned short* g;
        uint32_t so;
        int b = 0;
        if (sid < 256) {
            int row = sid >> 2, seg = sid & 3;
            so = row * 80u + seg * 16u;
            g = g_xh + (size_t)(n0 + row) * Dd + seg * 8;
        } else if (sid < 512) {
            int rid = sid - 256;
            int row = rid >> 2, seg = rid & 3;
            so = 5120u + row * 80u + seg * 16u;
            g = g_xl + (size_t)(n0 + row) * Dd + seg * 8;
        } else if (sid < 1024) {
            int rid = sid - 512;
            int row = rid >> 2, seg = rid & 3;
            so = 10240u + row * 80u + seg * 16u;
            g = g_W1TH + (size_t)row * Dd + seg * 8;
            b = 1;
        } else {
            int rid = sid - 1024;
            int row = rid >> 2, seg = rid & 3;
            so = 20480u + row * 80u + seg * 16u;
            g = g_W1TL + (size_t)row * Dd + seg * 8;
            b = 1;
        }
        sdst[j] = so;
        gsrc[j] = (const char*)g;
        isB[j] = b;
    }

    float acc[2][4][4];
#pragma unroll
    for (int a = 0; a < 2; a++)
#pragma unroll
        for (int b = 0; b < 4; b++)
#pragma unroll
            for (int c = 0; c < 4; c++) acc[a][b][c] = 0.f;

    uint32_t aoff = (uint32_t)((wy * 32 + (lane & 15)) * 80 + (lane >> 4) * 16);
    uint32_t boff = (uint32_t)((wx * 32 + ((lane & 7) | ((lane >> 4) << 3))) * 80 + ((lane >> 3) & 1) * 16);

    const int NCH = 32;
#pragma unroll
    for (int j = 0; j < 6; j++) {
        if (isB[j]) { CPASYNC16_CA(sb0 + sdst[j], gsrc[j]); }
        else        { CPASYNC16(sb0 + sdst[j], gsrc[j]); }
    }
    CP_COMMIT();
#pragma unroll
    for (int j = 0; j < 6; j++) {
        if (isB[j]) { CPASYNC16_CA(sb0 + BM_STAGE + sdst[j], gsrc[j] + 64); }
        else        { CPASYNC16(sb0 + BM_STAGE + sdst[j], gsrc[j] + 64); }
    }
    CP_COMMIT();

    for (int ch = 0; ch < NCH; ch++) {
        if (ch == NCH - 1) { CP_WAIT(0); } else { CP_WAIT(1); }
        __syncthreads();
        if (ch + 2 < NCH) {
            uint32_t stg = sb0 + ((ch + 2) % 3) * BM_STAGE;
            int cb = (ch + 2) * 64;
#pragma unroll
            for (int j = 0; j < 6; j++) {
                if (isB[j]) { CPASYNC16_CA(stg + sdst[j], gsrc[j] + cb); }
                else        { CPASYNC16(stg + sdst[j], gsrc[j] + cb); }
            }
            CP_COMMIT();
        }
        uint32_t s = sb0 + (ch % 3) * BM_STAGE;
#pragma unroll
        for (int k16 = 0; k16 < 2; k16++) {
            uint32_t kb = k16 * 32;
            uint32_t ah[2][4], al[2][4], bh[2][4], bl[2][4];
#pragma unroll
            for (int mt = 0; mt < 2; mt++) {
                LDSM4(ah[mt], s + aoff + mt * (16 * 80) + kb);
                LDSM4(al[mt], s + 5120 + aoff + mt * (16 * 80) + kb);
            }
#pragma unroll
            for (int nt = 0; nt < 2; nt++) {
                LDSM4(bh[nt], s + 10240 + boff + nt * (16 * 80) + kb);
                LDSM4(bl[nt], s + 20480 + boff + nt * (16 * 80) + kb);
            }
#pragma unroll
            for (int mt = 0; mt < 2; mt++)
#pragma unroll
                for (int nt = 0; nt < 2; nt++)
#pragma unroll
                    for (int h = 0; h < 2; h++) {
                        MMA16816(acc[mt][nt * 2 + h], ah[mt], bh[nt][2 * h], bh[nt][2 * h + 1]);
                        MMA16816(acc[mt][nt * 2 + h], ah[mt], bl[nt][2 * h], bl[nt][2 * h + 1]);
                        MMA16816(acc[mt][nt * 2 + h], al[mt], bh[nt][2 * h], bh[nt][2 * h + 1]);
                    }
        }
    }

#pragma unroll
    for (int mt = 0; mt < 2; mt++)
#pragma unroll
        for (int rh = 0; rh < 2; rh++) {
            int row = n0 + wy * 32 + mt * 16 + (lane >> 2) + rh * 8;
            const float* hb = g_hb + (row >> 11) * HIDk;
#pragma unroll
            for (int nq = 0; nq < 4; nq++) {
                int col = wx * 32 + nq * 8 + (lane & 3) * 2;
                g_base[(size_t)row * HIDk + col]     = acc[mt][nq][rh * 2]     + hb[col];
                g_base[(size_t)row * HIDk + col + 1] = acc[mt][nq][rh * 2 + 1] + hb[col + 1];
            }
        }
}

// ===================== merge: W' = W + A@B -> transposed fp16 hi =====================
__global__ __launch_bounds__(256) void merge_kernel(
    const float* __restrict__ Wgate, const float* __restrict__ Wup, const float* __restrict__ Wdown,
    const float* __restrict__ Ag, const float* __restrict__ Bg,
    const float* __restrict__ Au, const float* __restrict__ Bu,
    const float* __restrict__ Ad, const float* __restrict__ Bd) {
    __shared__ float As[128][17];
    __shared__ float Bs[16][65];
    __shared__ unsigned short Thi[64][136];
    int e = blockIdx.y, t = blockIdx.x, tid = threadIdx.x;
    const float *src, *Ap, *Bp;
    unsigned short *dhi;
    int r0, c0, rowStride, outStride;
    if (t < 352) {
        int kt = t / 44, ft = t % 44;
        r0 = kt * 128; c0 = ft * 64; rowStride = Ff; outStride = Dd;
        src = Wgate + (size_t)e * Dd * Ff; Ap = Ag + (size_t)e * Dd * Rr; Bp = Bg + (size_t)e * Rr * Ff;
        dhi = g_WgH + (size_t)e * Ff * Dd;
    } else if (t < 704) {
        t -= 352;
        int kt = t / 44, ft = t % 44;
        r0 = kt * 128; c0 = ft * 64; rowStride = Ff; outStride = Dd;
        src = Wup + (size_t)e * Dd * Ff; Ap = Au + (size_t)e * Dd * Rr; Bp = Bu + (size_t)e * Rr * Ff;
        dhi = g_WuH + (size_t)e * Ff * Dd;
    } else {
        t -= 704;
        int kt = t / 16, ft = t % 16;
        r0 = kt * 128; c0 = ft * 64; rowStride = Dd; outStride = Ff;
        src = Wdown + (size_t)e * Ff * Dd; Ap = Ad + (size_t)e * Ff * Rr; Bp = Bd + (size_t)e * Rr * Dd;
        dhi = g_WdH + (size_t)e * Dd * Ff;
    }
    {
        int r = tid >> 1, k0 = (tid & 1) * 8;
#pragma unroll
        for (int kk = 0; kk < 8; kk++)
            As[r][k0 + kk] = Ap[(size_t)(r0 + r) * Rr + k0 + kk];
    }
    for (int i = tid; i < 1024; i += 256) {
        int k = i >> 6, c = i & 63;
        Bs[k][c] = Bp[(size_t)k * rowStride + c0 + c];
    }
    __syncthreads();
    {
        int c = tid & 63, rb = tid >> 6;
        float vbuf[32];
        for (int rr = 0; rr < 32; rr++) {
            int r = rb * 32 + rr;
            float v = src[(size_t)(r0 + r) * rowStride + c0 + c];
#pragma unroll
            for (int k = 0; k < 16; k++) v += As[r][k] * Bs[k][c];
            vbuf[rr] = v;
        }
        for (int w = 0; w < 32; w++) {
            int rr = (w + c) & 31;
            Thi[c][rb * 32 + rr] = __half_as_ushort(__float2half_rn(vbuf[rr]));
        }
    }
    __syncthreads();
    {
        int c = tid >> 2, qq = tid & 3;
        const uint4* sh = (const uint4*)&Thi[c][qq * 32];
        uint4* dH = (uint4*)(dhi + (size_t)(c0 + c) * outStride + r0 + qq * 32);
#pragma unroll
        for (int m = 0; m < 4; m++) dH[m] = sh[m];
    }
}

// ===================== fused gate logits: 64 tokens x 2 experts per CTA =====================
#define L2_B0   69632
#define L2_BSTG 34816
#define L2_RED  (L2_B0 + 2 * L2_BSTG)
#define L2_B2   (L2_RED + 1536)
#define L2_CG   (L2_B2 + 4096)
#define L2_SMEM (L2_CG + 4096)

__global__ __launch_bounds__(256) void logits_kernel(const float* __restrict__ b2) {
    extern __shared__ char sm[];
    uint32_t sb = smem_u32(sm);
    int e0 = blockIdx.y * 2, n0 = blockIdx.x * 64;
    int tid = threadIdx.x, lane = tid & 31, wid = tid >> 5;
    int wy = wid & 3, wx = wid >> 2;

    {
        float* red = (float*)(sm + L2_RED);
        red[tid] = 0.f;
        if (tid < 128) red[tid + 256] = 0.f;
    }
#pragma unroll
    for (int i = 0; i < 4; i++) {
        ((float*)(sm + L2_B2))[tid + 256 * i] = b2[tid + 256 * i];
        ((float*)(sm + L2_CG))[tid + 256 * i] = g_cgw[tid + 256 * i];
    }
    {
        int t = tid >> 2, kq = (tid & 3) * 32;
        const float4* bp = (const float4*)(g_base + (size_t)(n0 + t) * HIDk + kq);
        const float4* p0 = (const float4*)(g_pk + e0 * HIDk + kq);
        const float4* p1 = (const float4*)(g_pk + (e0 + 1) * HIDk + kq);
        unsigned short* ah0 = (unsigned short*)(sm)          + t * 136 + kq;
        unsigned short* al0 = (unsigned short*)(sm + 17408)  + t * 136 + kq;
        unsigned short* ah1 = (unsigned short*)(sm + 34816)  + t * 136 + kq;
        unsigned short* al1 = (unsigned short*)(sm + 52224)  + t * 136 + kq;
#pragma unroll
        for (int q = 0; q < 8; q++) {
            float4 a = bp[q];
            float4 pa = p0[q], pb = p1[q];
            float v0[4] = {fmaxf(a.x + pa.x, 0.f), fmaxf(a.y + pa.y, 0.f),
                           fmaxf(a.z + pa.z, 0.f), fmaxf(a.w + pa.w, 0.f)};
            float v1[4] = {fmaxf(a.x + pb.x, 0.f), fmaxf(a.y + pb.y, 0.f),
                           fmaxf(a.z + pb.z, 0.f), fmaxf(a.w + pb.w, 0.f)};
#pragma unroll
            for (int c = 0; c < 4; c++) {
                unsigned short hi, lo;
                f2h_split(v0[c], hi, lo);
                ah0[q * 4 + c] = hi; al0[q * 4 + c] = lo;
                f2h_split(v1[c], hi, lo);
                ah1[q * 4 + c] = hi; al1[q * 4 + c] = lo;
            }
        }
    }
    uint32_t sdst[8];
    uint32_t gofs[8];
    int ghl[8];
#pragma unroll
    for (int j = 0; j < 8; j++) {
        int sid = tid + 256 * j;
        int hl = sid >> 10;
        int rid = sid & 1023;
        int row = rid >> 4, seg = rid & 15;
        sdst[j] = (uint32_t)(hl * 17408 + row * 272 + seg * 16);
        gofs[j] = (uint32_t)(row * HIDk + seg * 8);
        ghl[j] = hl;
    }
#pragma unroll
    for (int j = 0; j < 8; j++) {
        const unsigned short* g = (ghl[j] ? g_W2TL : g_W2TH) + gofs[j];
        CPASYNC16_CA(sb + L2_B0 + sdst[j], (const char*)g);
    }
    CP_COMMIT();
    __syncthreads();

    float s1[2][2] = {{0.f,0.f},{0.f,0.f}}, s2v[2][2] = {{0.f,0.f},{0.f,0.f}}, s3[2][2] = {{0.f,0.f},{0.f,0.f}};
    uint32_t aoff = (uint32_t)((wy * 16 + (lane & 15)) * 272 + (lane >> 4) * 16);
    uint32_t boff = (uint32_t)(((wx * 32 + ((lane & 7) | ((lane >> 4) << 3))) * 272) + ((lane >> 3) & 1) * 16);

    for (int ch = 0; ch < 16; ch++) {
        if (ch + 1 < 16) {
            uint32_t stg = sb + L2_B0 + ((ch + 1) & 1) * L2_BSTG;
            uint32_t dadd = (uint32_t)((ch + 1) * 64 * HIDk);
#pragma unroll
            for (int j = 0; j < 8; j++) {
                const unsigned short* g = (ghl[j] ? g_W2TL : g_W2TH) + gofs[j] + dadd;
                CPASYNC16_CA(stg + sdst[j], (const char*)g);
            }
            CP_COMMIT();
            CP_WAIT(1);
        } else {
            CP_WAIT(0);
        }
        __syncthreads();
        uint32_t sB = sb + L2_B0 + (ch & 1) * L2_BSTG;
        float acc[2][4][4];
#pragma unroll
        for (int e = 0; e < 2; e++)
#pragma unroll
            for (int a = 0; a < 4; a++)
#pragma unroll
                for (int c = 0; c < 4; c++) acc[e][a][c] = 0.f;
#pragma unroll
        for (int k16 = 0; k16 < 8; k16++) {
            uint32_t kb = (uint32_t)(k16 * 32);
            uint32_t bh[2][4], bl[2][4];
            LDSM4(bh[0], sB + boff + kb);
            LDSM4(bh[1], sB + boff + 16 * 272 + kb);
            LDSM4(bl[0], sB + 17408 + boff + kb);
            LDSM4(bl[1], sB + 17408 + boff + 16 * 272 + kb);
#pragma unroll
            for (int e = 0; e < 2; e++) {
                uint32_t ahr[4], alr[4];
                LDSM4(ahr, sb + e * 34816 + aoff + kb);
                LDSM4(alr, sb + e * 34816 + 17408 + aoff + kb);
#pragma unroll
                for (int nt = 0; nt < 2; nt++)
#pragma unroll
                    for (int h = 0; h < 2; h++) {
                        MMA16816(acc[e][nt * 2 + h], ahr, bh[nt][2 * h], bh[nt][2 * h + 1]);
                        MMA16816(acc[e][nt * 2 + h], alr, bh[nt][2 * h], bh[nt][2 * h + 1]);
                        MMA16816(acc[e][nt * 2 + h], ahr, bl[nt][2 * h], bl[nt][2 * h + 1]);
                    }
            }
        }
#pragma unroll
        for (int e = 0; e < 2; e++)
#pragma unroll
            for (int nt4 = 0; nt4 < 4; nt4++) {
                int col = ch * 64 + wx * 32 + nt4 * 8 + (lane & 3) * 2;
                float b0 = ((float*)(sm + L2_B2))[col], b1v = ((float*)(sm + L2_B2))[col + 1];
                float c0 = ((float*)(sm + L2_CG))[col], c1v = ((float*)(sm + L2_CG))[col + 1];
                float f;
                f = fmaxf(acc[e][nt4][0] + b0, 0.f);  s1[e][0] += f * c0;  s2v[e][0] += f; s3[e][0] += f * f;
                f = fmaxf(acc[e][nt4][1] + b1v, 0.f); s1[e][0] += f * c1v; s2v[e][0] += f; s3[e][0] += f * f;
                f = fmaxf(acc[e][nt4][2] + b0, 0.f);  s1[e][1] += f * c0;  s2v[e][1] += f; s3[e][1] += f * f;
                f = fmaxf(acc[e][nt4][3] + b1v, 0.f); s1[e][1] += f * c1v; s2v[e][1] += f; s3[e][1] += f * f;
            }
        __syncthreads();
    }
#pragma unroll
    for (int off = 1; off <= 2; off <<= 1) {
#pragma unroll
        for (int e = 0; e < 2; e++)
#pragma unroll
            for (int i = 0; i < 2; i++) {
                s1[e][i]  += __shfl_xor_sync(0xffffffffu, s1[e][i], off);
                s2v[e][i] += __shfl_xor_sync(0xffffffffu, s2v[e][i], off);
                s3[e][i]  += __shfl_xor_sync(0xffffffffu, s3[e][i], off);
            }
    }
    if ((lane & 3) == 0) {
        int row = wy * 16 + (lane >> 2);
        float* red = (float*)(sm + L2_RED);
#pragma unroll
        for (int e = 0; e < 2; e++) {
            atomicAdd(&red[e * 192 + row],           s1[e][0]);
            atomicAdd(&red[e * 192 + row + 8],       s1[e][1]);
            atomicAdd(&red[e * 192 + 64 + row],      s2v[e][0]);
            atomicAdd(&red[e * 192 + 64 + row + 8],  s2v[e][1]);
            atomicAdd(&red[e * 192 + 128 + row],     s3[e][0]);
            atomicAdd(&red[e * 192 + 128 + row + 8], s3[e][1]);
        }
    }
    __syncthreads();
    if (tid < 128) {
        int e = tid >> 6, t = tid & 63;
        float* red = (float*)(sm + L2_RED);
        float S1 = red[e * 192 + t], S2 = red[e * 192 + 64 + t], S3 = red[e * 192 + 128 + t];
        float Cg = g_CgCb[0], Cb = g_CgCb[1];
        float mu = S2 * (1.f / (float)Dd);
        float var = S3 * (1.f / (float)Dd) - mu * mu;
        float rstd = rsqrtf(var + LN_EPS);
        g_logits[(size_t)(n0 + t) * Ee + e0 + e] = rstd * (S1 - mu * Cg) + Cb;
    }
}

// ===================== routing =====================
__global__ void route_kernel() {
    int n = blockIdx.x * 256 + threadIdx.x;
    float l[Ee];
    float m = -1e30f;
#pragma unroll
    for (int e = 0; e < Ee; e++) { l[e] = g_logits[(size_t)n * Ee + e]; m = fmaxf(m, l[e]); }
    float s = 0.f;
#pragma unroll
    for (int e = 0; e < Ee; e++) { l[e] = expf(l[e] - m); s += l[e]; }
    float inv = 1.f / s;
#pragma unroll
    for (int e = 0; e < Ee; e++) l[e] *= inv;
    int i0 = 0; float b0 = l[0];
#pragma unroll
    for (int e = 1; e < Ee; e++) if (l[e] > b0) { b0 = l[e]; i0 = e; }
    int i1 = -1; float b1 = -1.f;
#pragma unroll
    for (int e = 0; e < Ee; e++) if (e != i0 && l[e] > b1) { b1 = l[e]; i1 = e; }
    int p0 = atomicAdd(&g_cnt[i0], 1);
    int p1 = atomicAdd(&g_cnt[i1], 1);
    g_te[2 * n] = i0; g_tp[2 * n] = p0; g_tw[2 * n] = b0;
    g_te[2 * n + 1] = i1; g_tp[2 * n + 1] = p1; g_tw[2 * n + 1] = b1;
}

// scatter with local prefix scan
__global__ void scatter_kernel() {
    __shared__ int soff[Ee];
    if (threadIdx.x == 0) {
        int a = 0;
        for (int e = 0; e < Ee; e++) { soff[e] = a; a += g_cnt[e]; }
        if (blockIdx.x == 0)
            for (int e = 0; e < Ee; e++) g_off[e] = soff[e];
    }
    __syncthreads();
    int n = blockIdx.x * 256 + threadIdx.x;
#pragma unroll
    for (int i = 0; i < 2; i++) {
        int slot = soff[g_te[2 * n + i]] + g_tp[2 * n + i];
        g_ptok[slot] = n;
        g_pw[slot] = g_tw[2 * n + i];
    }
}

// ===================== expert GEMM1 (1-term; 128 tok x 64 f gate+up; 4-stage; 2 CTA/SM) =====================
#define G1_STAGE 20480
#define G1_SMEM (1024 + 4 * G1_STAGE)

__global__ __launch_bounds__(256, 2) void moe_gemm1() {
    extern __shared__ char sm[];
    int e = blockIdx.z;
    int cnt = g_cnt[e];
    int r0 = blockIdx.y * 128;
    if (r0 >= cnt) return;
    int off = g_off[e];
    int f0 = blockIdx.x * 64;
    int tid = threadIdx.x, lane = tid & 31, wid = tid >> 5;
    int wy = wid & 3, wx = wid >> 2;

    int* stok = (int*)sm;
    if (tid < 128) {
        int lr = r0 + tid; if (lr >= cnt) lr = cnt - 1;
        stok[tid] = g_ptok[off + lr];
    }
    __syncthreads();

    uint32_t sb0 = smem_u32(sm) + 1024;

    uint32_t sdst[4];
    const char* gsrc[4];
    int isA[4];
#pragma unroll
    for (int j = 0; j < 4; j++) {
        int sid = tid + 256 * j;
        int region = sid >> 9;
        int rid = sid & 511;
        int row = rid >> 2, seg = rid & 3;
        sdst[j] = (uint32_t)(region * 10240 + row * 80 + seg * 16);
        const unsigned short* g;
        if (region == 0) g = g_xh + (size_t)stok[row] * Dd;
        else             g = (row < 64) ? g_WgH + ((size_t)e * Ff + f0 + row) * Dd
                                        : g_WuH + ((size_t)e * Ff + f0 + row - 64) * Dd;
        gsrc[j] = (const char*)(g + seg * 8);
        isA[j] = (region == 0);
    }

    float accG[2][4][4], accU[2][4][4];
#pragma unroll
    for (int a = 0; a < 2; a++)
#pragma unroll
        for (int b = 0; b < 4; b++)
#pragma unroll
            for (int c = 0; c < 4; c++) { accG[a][b][c] = 0.f; accU[a][b][c] = 0.f; }

    uint32_t aoff = (uint32_t)((wy * 32 + (lane & 15)) * 80 + (lane >> 4) * 16);
    uint32_t boff = (uint32_t)((wx * 32 + ((lane & 7) | ((lane >> 4) << 3))) * 80 + ((lane >> 3) & 1) * 16);

    const int NCH = 32;
#pragma unroll
    for (int p = 0; p < 3; p++) {
#pragma unroll
        for (int j = 0; j < 4; j++) {
            if (isA[j]) { CPASYNC16_CA(sb0 + p * G1_STAGE + sdst[j], gsrc[j] + p * 64); }
            else        { CPASYNC16(sb0 + p * G1_STAGE + sdst[j], gsrc[j] + p * 64); }
        }
        CP_COMMIT();
    }

    for (int ch = 0; ch < NCH; ch++) {
        if (ch >= NCH - 3) { CP_WAIT(0); } else { CP_WAIT(2); }
        __syncthreads();
        if (ch + 3 < NCH) {
            uint32_t stg = sb0 + ((ch + 3) & 3) * G1_STAGE;
            int cb = (ch + 3) * 64;
#pragma unroll
            for (int j = 0; j < 4; j++) {
                if (isA[j]) { CPASYNC16_CA(stg + sdst[j], gsrc[j] + cb); }
                else        { CPASYNC16(stg + sdst[j], gsrc[j] + cb); }
            }
            CP_COMMIT();
        }
        uint32_t s = sb0 + (ch & 3) * G1_STAGE;
#pragma unroll
        for (int k16 = 0; k16 < 2; k16++) {
            uint32_t kb = k16 * 32;
            uint32_t ah[2][4], bg[2][4], bu[2][4];
#pragma unroll
            for (int mt = 0; mt < 2; mt++)
                LDSM4(ah[mt], s + aoff + mt * (16 * 80) + kb);
#pragma unroll
            for (int nt = 0; nt < 2; nt++) {
                LDSM4(bg[nt], s + 10240 + boff + nt * (16 * 80) + kb);
                LDSM4(bu[nt], s + 10240 + 5120 + boff + nt * (16 * 80) + kb);
            }
#pragma unroll
            for (int mt = 0; mt < 2; mt++)
#pragma unroll
                for (int nt = 0; nt < 2; nt++)
#pragma unroll
                    for (int h = 0; h < 2; h++) {
                        MMA16816(accG[mt][nt * 2 + h], ah[mt], bg[nt][2 * h], bg[nt][2 * h + 1]);
                        MMA16816(accU[mt][nt * 2 + h], ah[mt], bu[nt][2 * h], bu[nt][2 * h + 1]);
                    }
        }
    }

#pragma unroll
    for (int mt = 0; mt < 2; mt++)
#pragma unroll
        for (int rh = 0; rh < 2; rh++) {
            int lr = wy * 32 + mt * 16 + (lane >> 2) + rh * 8;
            if (r0 + lr < cnt) {
                int slot = off + r0 + lr;
#pragma unroll
                for (int nt8 = 0; nt8 < 4; nt8++) {
                    int col = f0 + wx * 32 + nt8 * 8 + (lane & 3) * 2;
                    float g0 = accG[mt][nt8][rh * 2 + 0], g1 = accG[mt][nt8][rh * 2 + 1];
                    float u0 = accU[mt][nt8][rh * 2 + 0], u1 = accU[mt][nt8][rh * 2 + 1];
                    float h0 = g0 / (1.f + __expf(-g0)) * u0;
                    float h1 = g1 / (1.f + __expf(-g1)) * u1;
                    unsigned short a0 = __half_as_ushort(__float2half_rn(h0));
                    unsigned short a1 = __half_as_ushort(__float2half_rn(h1));
                    size_t idx = ((size_t)slot * Ff + col) >> 1;
                    ((uint32_t*)g_Hh)[idx] = (uint32_t)a0 | ((uint32_t)a1 << 16);
                }
            }
        }
}

// ===================== expert GEMM2 (1-term; 128x128; 4-stage; 2 CTA/SM; plain-store epilogue) =====================
#define G2_STAGE 20480
#define G2_SMEM (4 * G2_STAGE)

__global__ __launch_bounds__(256, 2) void moe_gemm2() {
    extern __shared__ char sm[];
    int e = blockIdx.z;
    int cnt = g_cnt[e];
    int r0 = blockIdx.y * 128;
    if (r0 >= cnt) return;
    int off = g_off[e];
    int d0 = blockIdx.x * 128;
    int tid = threadIdx.x, lane = tid & 31, wid = tid >> 5;
    int wy = wid & 3, wx = wid >> 2;

    uint32_t sb0 = smem_u32(sm);

    uint32_t sdst[4];
    const char* gsrc[4];
    int isA[4];
#pragma unroll
    for (int j = 0; j < 4; j++) {
        int sid = tid + 256 * j;
        const unsigned short* g;
        uint32_t so;
        int a = 0;
        if (sid < 512) {
            int row = sid >> 2, seg = sid & 3;
            so = row * 80u + seg * 16u;
            int lr = r0 + row; if (lr >= cnt) lr = cnt - 1;
            g = g_Hh + (size_t)(off + lr) * Ff + seg * 8;
            a = 1;
        } else {
            int rid = sid - 512;
            int row = rid >> 2, seg = rid & 3;
            so = 10240u + row * 80u + seg * 16u;
            g = g_WdH + ((size_t)e * Dd + d0 + row) * Ff + seg * 8;
        }
        sdst[j] = so;
        gsrc[j] = (const char*)g;
        isA[j] = a;
    }

    float acc[2][8][4];
#pragma unroll
    for (int a = 0; a < 2; a++)
#pragma unroll
        for (int b = 0; b < 8; b++)
#pragma unroll
            for (int c = 0; c < 4; c++) acc[a][b][c] = 0.f;

    uint32_t aoff = (uint32_t)((wy * 32 + (lane & 15)) * 80 + (lane >> 4) * 16);
    uint32_t boff = (uint32_t)((wx * 64 + ((lane & 7) | ((lane >> 4) << 3))) * 80 + ((lane >> 3) & 1) * 16);

    const int NCH = 88;
#pragma unroll
    for (int p = 0; p < 3; p++) {
#pragma unroll
        for (int j = 0; j < 4; j++) {
            if (isA[j]) { CPASYNC16_CA(sb0 + p * G2_STAGE + sdst[j], gsrc[j] + p * 64); }
            else        { CPASYNC16(sb0 + p * G2_STAGE + sdst[j], gsrc[j] + p * 64); }
        }
        CP_COMMIT();
    }

    for (int ch = 0; ch < NCH; ch++) {
        if (ch >= NCH - 3) { CP_WAIT(0); } else { CP_WAIT(2); }
        __syncthreads();
        if (ch + 3 < NCH) {
            uint32_t stg = sb0 + ((ch + 3) & 3) * G2_STAGE;
            int cb = (ch + 3) * 64;
#pragma unroll
            for (int j = 0; j < 4; j++) {
                if (isA[j]) { CPASYNC16_CA(stg + sdst[j], gsrc[j] + cb); }
                else        { CPASYNC16(stg + sdst[j], gsrc[j] + cb); }
            }
            CP_COMMIT();
        }
        uint32_t s = sb0 + (ch & 3) * G2_STAGE;
#pragma unroll
        for (int k16 = 0; k16 < 2; k16++) {
            uint32_t kb = k16 * 32;
            uint32_t ah[2][4], bf[4][4];
#pragma unroll
            for (int mt = 0; mt < 2; mt++)
                LDSM4(ah[mt], s + aoff + mt * (16 * 80) + kb);
#pragma unroll
            for (int nt = 0; nt < 4; nt++) LDSM4(bf[nt], s + 10240 + boff + nt * (16 * 80) + kb);
#pragma unroll
            for (int mt = 0; mt < 2; mt++)
#pragma unroll
                for (int nt = 0; nt < 4; nt++)
#pragma unroll
                    for (int h = 0; h < 2; h++)
                        MMA16816(acc[mt][nt * 2 + h], ah[mt], bf[nt][2 * h], bf[nt][2 * h + 1]);
        }
    }

#pragma unroll
    for (int mt = 0; mt < 2; mt++)
#pragma unroll
        for (int rh = 0; rh < 2; rh++) {
            int lr = wy * 32 + mt * 16 + (lane >> 2) + rh * 8;
            if (r0 + lr < cnt) {
                int slot = off + r0 + lr;
                float w = g_pw[slot];
                float* op = g_Op + (size_t)slot * Dd + d0 + wx * 64 + (lane & 3) * 2;
#pragma unroll
                for (int nt8 = 0; nt8 < 8; nt8++) {
                    float2 v = make_float2(acc[mt][nt8][rh * 2 + 0] * w,
                                           acc[mt][nt8][rh * 2 + 1] * w);
                    *(float2*)(op + nt8 * 8) = v;
                }
            }
        }
}

// ===================== combine: out[tok] = Op[slot0] + Op[slot1] =====================
__global__ void combine_kernel(float* __restrict__ out) {
    size_t i = (size_t)blockIdx.x * 256 + threadIdx.x;
    int tok = (int)(i >> 8);
    int q = (int)(i & 255);
    int s0 = g_off[g_te[2 * tok]]     + g_tp[2 * tok];
    int s1 = g_off[g_te[2 * tok + 1]] + g_tp[2 * tok + 1];
    float4 a = ((const float4*)(g_Op + (size_t)s0 * Dd))[q];
    float4 b = ((const float4*)(g_Op + (size_t)s1 * Dd))[q];
    float4 r = make_float4(a.x + b.x, a.y + b.y, a.z + b.z, a.w + b.w);
    ((float4*)(out + (size_t)tok * Dd))[q] = r;
}

// ===================== launch =====================
extern "C" void kernel_launch(void* const* d_in, const int* in_sizes, int n_in,
                              void* d_out, int out_size) {
    (void)in_sizes; (void)n_in; (void)out_size;
    const float* x       = (const float*)d_in[0];
    const float* hist    = (const float*)d_in[1];
    const float* persona = (const float*)d_in[2];
    const float* W1x     = (const float*)d_in[3];
    const float* W1h     = (const float*)d_in[4];
    const float* W1p     = (const float*)d_in[5];
    const float* b1      = (const float*)d_in[6];
    const float* W2      = (const float*)d_in[7];
    const float* b2      = (const float*)d_in[8];
    const float* ln_g    = (const float*)d_in[9];
    const float* ln_b    = (const float*)d_in[10];
    const float* Wg      = (const float*)d_in[11];
    const float* bg      = (const float*)d_in[12];
    const float* Wgate   = (const float*)d_in[13];
    const float* Wup     = (const float*)d_in[14];
    const float* Wdown   = (const float*)d_in[15];
    const float* Ag      = (const float*)d_in[16];
    const float* Bg      = (const float*)d_in[17];
    const float* Au      = (const float*)d_in[18];
    const float* Bu      = (const float*)d_in[19];
    const float* Ad      = (const float*)d_in[20];
    const float* Bd      = (const float*)d_in[21];
    float* out = (float*)d_out;

    static cudaStream_t s2 = nullptr;
    static cudaEvent_t evFork = nullptr, evJoin = nullptr;
    if (!s2) {
        cudaStreamCreateWithFlags(&s2, cudaStreamNonBlocking);
        cudaEventCreateWithFlags(&evFork, cudaEventDisableTiming);
        cudaEventCreateWithFlags(&evJoin, cudaEventDisableTiming);
    }

    cudaFuncSetAttribute(moe_gemm1, cudaFuncAttributeMaxDynamicSharedMemorySize, G1_SMEM);
    cudaFuncSetAttribute(moe_gemm2, cudaFuncAttributeMaxDynamicSharedMemorySize, G2_SMEM);
    cudaFuncSetAttribute(logits_kernel, cudaFuncAttributeMaxDynamicSharedMemorySize, L2_SMEM);
    cudaFuncSetAttribute(base_mma, cudaFuncAttributeMaxDynamicSharedMemorySize, BM_SMEM);

    void* cntp = nullptr;
    cudaGetSymbolAddress(&cntp, g_cnt);

    cudaMemsetAsync(cntp, 0, Ee * sizeof(int));

    cudaEventRecord(evFork, 0);
    cudaStreamWaitEvent(s2, evFork, 0);
    merge_kernel<<<dim3(1056, Ee), 256, 0, s2>>>(Wgate, Wup, Wdown, Ag, Bg, Au, Bu, Ad, Bd);
    cudaEventRecord(evJoin, s2);

    prep_kernel<<<13, 128>>>(hist, W1h, b1, persona, W1p, ln_g, ln_b, Wg, bg);
    w2t_kernel<<<dim3(Dd / 32, HIDk / 32), 256>>>(W2);
    w1t_kernel<<<dim3(HIDk / 32, Dd / 32), 256>>>(W1x);
    xconv_kernel<<<(Nn * Dd) / 4 / 256, 256>>>(x);
    base_mma<<<Nn / 64, 256, BM_SMEM>>>();
    logits_kernel<<<dim3(Nn / 64, Ee / 2), 256, L2_SMEM>>>(b2);
    route_kernel<<<Nn / 256, 256>>>();
    scatter_kernel<<<Nn / 256, 256>>>();

    cudaStreamWaitEvent(0, evJoin, 0);
    // per-expert count <= Nn (8192) -> at most 64 rowtiles of 128 can have work
    moe_gemm1<<<dim3(Ff / 64, Nn / 128, Ee), 256, G1_SMEM>>>();
    moe_gemm2<<<dim3(Dd / 128, Nn / 128, Ee), 256, G2_SMEM>>>();
    combine_kernel<<<(Nn * Dd) / 4 / 256, 256>>>(out);
}